// round 16
// baseline (speedup 1.0000x reference)
#include <cuda_runtime.h>
#include <cstdint>
#include <cstddef>

// ---------------- problem constants ----------------
#define FANOUT 10
#define N0_SZ 1362944
#define N1_SZ 123904
#define N2_SZ 11264
#define SEEDS_SZ 1024
#define IN_DIM 256
#define H_DIM 512
#define C_DIM 256

#define NUNITS (N1_SZ / 128)        // 968 layer-0 M-tiles
#define GATHER_CTAS 96

// ---------------- device scratch (allocation-free rule) ----------------
__device__ __align__(16) float g_xr[(size_t)N1_SZ * IN_DIM];
__device__ __align__(16) float g_neigh0[(size_t)N1_SZ * IN_DIM];
__device__ __align__(16) float g_h1[(size_t)N1_SZ * H_DIM];
__device__ __align__(16) float g_neigh1[(size_t)N2_SZ * H_DIM];
__device__ __align__(16) float g_h2[(size_t)N2_SZ * H_DIM];
__device__ __align__(16) float g_neigh2[(size_t)SEEDS_SZ * H_DIM];
__device__ __align__(16) float g_Wt0s[(size_t)H_DIM * IN_DIM];
__device__ __align__(16) float g_Wt0n[(size_t)H_DIM * IN_DIM];
__device__ __align__(16) float g_Wt1s[(size_t)H_DIM * H_DIM];
__device__ __align__(16) float g_Wt1n[(size_t)H_DIM * H_DIM];
__device__ __align__(16) float g_Wt2s[(size_t)C_DIM * H_DIM];
__device__ __align__(16) float g_Wt2n[(size_t)C_DIM * H_DIM];
__device__ volatile unsigned g_ready0[NUNITS];

// ---------------- helpers (portable sm_80+ PTX) ----------------
__device__ __forceinline__ uint32_t smem_u32(const void* p) {
    uint32_t a;
    asm("{ .reg .u64 t; cvta.to.shared.u64 t, %1; cvt.u32.u64 %0, t; }" : "=r"(a) : "l"(p));
    return a;
}
__device__ __forceinline__ float cvt_tf32(float x) {
    float r; asm("cvt.rna.tf32.f32 %0, %1;" : "=f"(r) : "f"(x)); return r;
}
__device__ __forceinline__ void cp_async16(uint32_t dst, const void* src) {
    asm volatile("cp.async.cg.shared.global [%0], [%1], 16;" :: "r"(dst), "l"(src));
}
#define CP_COMMIT() asm volatile("cp.async.commit_group;" ::: "memory")
#define CP_WAIT(n)  asm volatile("cp.async.wait_group %0;" :: "n"(n) : "memory")

__device__ __forceinline__ void mma_tf32(float c[4],
                                         uint32_t a0, uint32_t a1, uint32_t a2, uint32_t a3,
                                         uint32_t b0, uint32_t b1) {
    asm volatile(
        "mma.sync.aligned.m16n8k8.row.col.f32.tf32.tf32.f32 "
        "{%0,%1,%2,%3}, {%4,%5,%6,%7}, {%8,%9}, {%0,%1,%2,%3};"
        : "+f"(c[0]), "+f"(c[1]), "+f"(c[2]), "+f"(c[3])
        : "r"(a0), "r"(a1), "r"(a2), "r"(a3), "r"(b0), "r"(b1));
}

__host__ __device__ __forceinline__ int perm8(int i) { return (i & 3) * 2 + (i >> 2); }

#define PADK 40
#define A_TILE_F (128 * PADK)               // 5120 floats
#define SMEM_GEMM_BYTES (4 * A_TILE_F * 4)  // 256-thr BN=128 GEMM: 80KB
#define STAGE_W64_F (2 * A_TILE_F)          // A+B per stage (both 128x32)
#define SMEM_W64_BYTES (2 * STAGE_W64_F * 4) // 80KB (2 stages)

// ---------------------------------------------------------------------------
// Layer-0 fused producer/consumer kernel — R8-EXACT.
// ---------------------------------------------------------------------------
__global__ __launch_bounds__(256, 2)
void layer0_fused_kernel(const float* __restrict__ x, const int* __restrict__ e0,
                         float* __restrict__ neigh0, float* __restrict__ xr,
                         const float* __restrict__ B0t, const float* __restrict__ B1t,
                         const float* __restrict__ bias, float* __restrict__ C) {
    extern __shared__ float sm[];
    const int tid = threadIdx.x;

    if (blockIdx.x < GATHER_CTAS) {
        const int t = tid & 31;
        const int ry = tid >> 5;
        const int dim8 = IN_DIM / 8;     // 32
        const float4* x4 = (const float4*)x;

        for (int u = blockIdx.x; u < NUNITS; u += GATHER_CTAS) {
            const int dbase = u * 128;
#pragma unroll 1
            for (int pass = 0; pass < 16; ++pass) {
                const int d = dbase + pass * 8 + ry;
                const int* s = e0 + (size_t)d * FANOUT;

                float4 a0 = make_float4(0.f, 0.f, 0.f, 0.f);
                float4 a1 = make_float4(0.f, 0.f, 0.f, 0.f);
#pragma unroll
                for (int e = 0; e < FANOUT; ++e) {
                    int r = __ldg(s + e);
                    const float4* p = x4 + ((size_t)r * dim8 + t) * 2;
                    float4 v0 = __ldg(p), v1 = __ldg(p + 1);
                    a0.x += v0.x; a0.y += v0.y; a0.z += v0.z; a0.w += v0.w;
                    a1.x += v1.x; a1.y += v1.y; a1.z += v1.z; a1.w += v1.w;
                }
                const float inv = 1.0f / FANOUT;
                a0.x = cvt_tf32(a0.x * inv); a0.y = cvt_tf32(a0.y * inv);
                a0.z = cvt_tf32(a0.z * inv); a0.w = cvt_tf32(a0.w * inv);
                a1.x = cvt_tf32(a1.x * inv); a1.y = cvt_tf32(a1.y * inv);
                a1.z = cvt_tf32(a1.z * inv); a1.w = cvt_tf32(a1.w * inv);

                float4* o = (float4*)neigh0 + ((size_t)d * dim8 + t) * 2;
                o[0] = make_float4(a0.x, a1.x, a0.y, a1.y);
                o[1] = make_float4(a0.z, a1.z, a0.w, a1.w);

                const float4* p = x4 + ((size_t)d * dim8 + t) * 2;
                float4 v0 = __ldg(p), v1 = __ldg(p + 1);
                v0.x = cvt_tf32(v0.x); v0.y = cvt_tf32(v0.y);
                v0.z = cvt_tf32(v0.z); v0.w = cvt_tf32(v0.w);
                v1.x = cvt_tf32(v1.x); v1.y = cvt_tf32(v1.y);
                v1.z = cvt_tf32(v1.z); v1.w = cvt_tf32(v1.w);
                float4* ox = (float4*)xr + ((size_t)d * dim8 + t) * 2;
                ox[0] = make_float4(v0.x, v1.x, v0.y, v1.y);
                ox[1] = make_float4(v0.z, v1.z, v0.w, v1.w);
            }
            __threadfence();
            __syncthreads();
            if (tid == 0) g_ready0[u] = 1;
        }
        return;
    }

    // GEMM consumer (K=256, N=512, BN=128)
    const int gbid = (int)blockIdx.x - GATHER_CTAS;
    const int n0 = (gbid & 3) * 128;
    const int mu = gbid >> 2;
    const int m0 = mu * 128;

    if (tid == 0) {
        while (g_ready0[mu] == 0) { __nanosleep(128); }
    }
    __syncthreads();

    const uint32_t sbase = smem_u32(sm);
    const int lane = tid & 31, w = tid >> 5;
    const int wm = w >> 2, wn = w & 3;
    const int K = IN_DIM, N = H_DIM;
    const int kc = K / 32, T = 2 * kc;

    float acc[4][4][4];
#pragma unroll
    for (int mi = 0; mi < 4; ++mi)
#pragma unroll
        for (int ni = 0; ni < 4; ++ni)
#pragma unroll
            for (int r = 0; r < 4; ++r) acc[mi][ni][r] = 0.f;

    const int srow = tid >> 3, sc4 = tid & 7;

    auto stage = [&](int chunk, int buf) {
        const int pair = (chunk >= kc) ? 1 : 0;
        const int k0 = (pair ? chunk - kc : chunk) * 32;
        const float* A = pair ? neigh0 : xr;
        const float* B = pair ? B1t : B0t;
        const uint32_t da = sbase + (uint32_t)buf * (A_TILE_F * 4);
        const uint32_t db = sbase + (uint32_t)(2 + buf) * (A_TILE_F * 4);
#pragma unroll
        for (int l = 0; l < 4; ++l) {
            int row = srow + l * 32;
            cp_async16(da + (uint32_t)(row * PADK + sc4 * 4) * 4,
                       A + (size_t)(m0 + row) * K + k0 + sc4 * 4);
        }
#pragma unroll
        for (int l = 0; l < 4; ++l) {
            int row = srow + l * 32;
            cp_async16(db + (uint32_t)(row * PADK + sc4 * 4) * 4,
                       B + (size_t)(n0 + row) * K + k0 + sc4 * 4);
        }
        CP_COMMIT();
    };

    stage(0, 0);
    int buf = 0;
    const int q2 = (lane & 3) * 2;
    const int rr = lane >> 2;

    for (int c = 0; c < T; ++c) {
        if (c + 1 < T) { stage(c + 1, buf ^ 1); CP_WAIT(1); }
        else           { CP_WAIT(0); }
        __syncthreads();

        const float* As = sm + buf * A_TILE_F;
        const float* Bs = sm + (2 + buf) * A_TILE_F;
#pragma unroll
        for (int ks = 0; ks < 4; ++ks) {
            uint32_t a[4][4], b[4][2];
            const int cc = ks * 8 + q2;
#pragma unroll
            for (int mi = 0; mi < 4; ++mi) {
                const float* p = As + (wm * 64 + mi * 16 + rr) * PADK + cc;
                float2 lo = *(const float2*)p;
                float2 hi = *(const float2*)(p + 8 * PADK);
                a[mi][0] = __float_as_uint(lo.x);
                a[mi][1] = __float_as_uint(hi.x);
                a[mi][2] = __float_as_uint(lo.y);
                a[mi][3] = __float_as_uint(hi.y);
            }
#pragma unroll
            for (int ni = 0; ni < 4; ++ni) {
                const float* p = Bs + (wn * 32 + ni * 8 + rr) * PADK + cc;
                float2 v = *(const float2*)p;
                b[ni][0] = __float_as_uint(v.x);
                b[ni][1] = __float_as_uint(v.y);
            }
#pragma unroll
            for (int mi = 0; mi < 4; ++mi)
#pragma unroll
                for (int ni = 0; ni < 4; ++ni)
                    mma_tf32(acc[mi][ni], a[mi][0], a[mi][1], a[mi][2], a[mi][3],
                             b[ni][0], b[ni][1]);
        }
        __syncthreads();
        buf ^= 1;
    }

#pragma unroll
    for (int ni = 0; ni < 4; ++ni) {
        const int n = n0 + wn * 32 + ni * 8 + 2 * (lane & 3);
        const float bx = __ldg(bias + n), by = __ldg(bias + n + 1);
#pragma unroll
        for (int mi = 0; mi < 4; ++mi) {
            const int m = m0 + wm * 64 + mi * 16 + (lane >> 2);
            float v00 = cvt_tf32(fmaxf(acc[mi][ni][0] + bx, 0.f));
            float v01 = cvt_tf32(fmaxf(acc[mi][ni][1] + by, 0.f));
            float v10 = cvt_tf32(fmaxf(acc[mi][ni][2] + bx, 0.f));
            float v11 = cvt_tf32(fmaxf(acc[mi][ni][3] + by, 0.f));
            const int g = n & ~7;
            const int p0 = g | perm8(n & 7), p1 = g | perm8((n + 1) & 7);
            C[(size_t)m * N + p0] = v00;
            C[(size_t)m * N + p1] = v01;
            C[(size_t)(m + 8) * N + p0] = v10;
            C[(size_t)(m + 8) * N + p1] = v11;
        }
    }
}

// ---------------------------------------------------------------------------
// gather-mean, layout-preserving (gather1, gather2) — whole-chip
// ---------------------------------------------------------------------------
__global__ void gather_mean_kernel(const float* __restrict__ h,
                                   const int* __restrict__ src,
                                   float* __restrict__ out, int dim8, int num_dst) {
    const int d = blockIdx.x * blockDim.y + threadIdx.y;
    if (d >= num_dst) return;
    const int t = threadIdx.x;
    const int* s = src + (size_t)d * FANOUT;
    const float4* h4 = (const float4*)h;

    float4 a0 = make_float4(0.f, 0.f, 0.f, 0.f);
    float4 a1 = make_float4(0.f, 0.f, 0.f, 0.f);
#pragma unroll
    for (int e = 0; e < FANOUT; ++e) {
        int r = __ldg(s + e);
        const float4* p = h4 + ((size_t)r * dim8 + t) * 2;
        float4 v0 = __ldg(p), v1 = __ldg(p + 1);
        a0.x += v0.x; a0.y += v0.y; a0.z += v0.z; a0.w += v0.w;
        a1.x += v1.x; a1.y += v1.y; a1.z += v1.z; a1.w += v1.w;
    }
    const float inv = 1.0f / FANOUT;
    a0.x = cvt_tf32(a0.x * inv); a0.y = cvt_tf32(a0.y * inv);
    a0.z = cvt_tf32(a0.z * inv); a0.w = cvt_tf32(a0.w * inv);
    a1.x = cvt_tf32(a1.x * inv); a1.y = cvt_tf32(a1.y * inv);
    a1.z = cvt_tf32(a1.z * inv); a1.w = cvt_tf32(a1.w * inv);

    float4* o = (float4*)out + ((size_t)d * dim8 + t) * 2;
    o[0] = a0;
    o[1] = a1;
}

// ---------------------------------------------------------------------------
// Merged weight transpose (6 jobs) + flag clear, ONE launch.
// ---------------------------------------------------------------------------
__global__ void transpose_all_kernel(const float* W0, float* D0,
                                     const float* W1, float* D1,
                                     const float* W2, float* D2,
                                     const float* W3, float* D3,
                                     const float* W4, float* D4,
                                     const float* W5, float* D5) {
    const int b = blockIdx.x;
    const int tid = threadIdx.y * 32 + threadIdx.x;
    if (b == 0) {
        for (int i = tid; i < NUNITS; i += 256) g_ready0[i] = 0;
    }
    const float* W; float* Wt; int K, N, t;
    if (b < 256) {
        K = IN_DIM; N = H_DIM;
        if (b < 128) { W = W0; Wt = D0; t = b; }
        else         { W = W1; Wt = D1; t = b - 128; }
    } else if (b < 768) {
        K = H_DIM; N = H_DIM;
        if (b < 512) { W = W2; Wt = D2; t = b - 256; }
        else         { W = W3; Wt = D3; t = b - 512; }
    } else {
        K = H_DIM; N = C_DIM;
        if (b < 896) { W = W4; Wt = D4; t = b - 768; }
        else         { W = W5; Wt = D5; t = b - 896; }
    }
    const int ntx = N / 32;
    const int bx = (t % ntx) * 32, by = (t / ntx) * 32;

    __shared__ float tile[32][33];
#pragma unroll
    for (int i = threadIdx.y; i < 32; i += 8)
        tile[i][threadIdx.x] = __ldg(W + (size_t)(by + i) * N + bx + threadIdx.x);
    __syncthreads();
#pragma unroll
    for (int i = threadIdx.y; i < 32; i += 8) {
        int k = by + threadIdx.x;
        int kp = (k & ~7) | perm8(k & 7);
        Wt[(size_t)(bx + i) * K + kp] = cvt_tf32(tile[threadIdx.x][i]);
    }
}

// ---------------------------------------------------------------------------
// NEW: warp-tile-64x64 tf32 GEMM. 128 threads, 4 warps (2m x 2n), CTA 128x128.
// Halves smem-crossbar bytes per MAC (0.125 vs 0.1875 B/MAC). 2 CTAs/SM @80KB.
// ---------------------------------------------------------------------------
template <bool INTERMEDIATE>
__global__ __launch_bounds__(128, 2)
void sage_mma_gemm_w64(const float* __restrict__ A0, const float* __restrict__ A1,
                       const float* __restrict__ B0t, const float* __restrict__ B1t,
                       const float* __restrict__ bias, float* __restrict__ C,
                       int K, int N) {
    extern __shared__ float sm[];
    const uint32_t sbase = smem_u32(sm);
    const int tid = threadIdx.x, lane = tid & 31, w = tid >> 5;
    const int wm = w >> 1, wn = w & 1;       // 2 x 2 warp grid, 64x64 tiles
    const int m0 = blockIdx.y * 128, n0 = blockIdx.x * 128;
    const int kc = K / 32, T = 2 * kc;

    float acc[4][8][4];
#pragma unroll
    for (int mi = 0; mi < 4; ++mi)
#pragma unroll
        for (int ni = 0; ni < 8; ++ni)
#pragma unroll
            for (int r = 0; r < 4; ++r) acc[mi][ni][r] = 0.f;

    auto stage = [&](int chunk, int buf) {
        const int pair = (chunk >= kc) ? 1 : 0;
        const int k0 = (pair ? chunk - kc : chunk) * 32;
        const float* A = pair ? A1 : A0;
        const float* B = pair ? B1t : B0t;
        const uint32_t da = sbase + (uint32_t)(buf * STAGE_W64_F) * 4;
        const uint32_t db = da + (uint32_t)A_TILE_F * 4;
        // A: 128 rows x 32 floats = 512 cp16 -> 4/thread
#pragma unroll
        for (int l = 0; l < 4; ++l) {
            int i = tid + l * 128;
            int row = i >> 2, c4 = i & 3;
            cp_async16(da + (uint32_t)(row * PADK + c4 * 8) * 4,
                       A + (size_t)(m0 + row) * K + k0 + c4 * 8);
            cp_async16(da + (uint32_t)(row * PADK + c4 * 8 + 4) * 4,
                       A + (size_t)(m0 + row) * K + k0 + c4 * 8 + 4);
        }
        // B: 128 rows x 32 floats = 512 cp16 -> 4/thread (paired like A)
#pragma unroll
        for (int l = 0; l < 4; ++l) {
            int i = tid + l * 128;
            int row = i >> 2, c4 = i & 3;
            cp_async16(db + (uint32_t)(row * PADK + c4 * 8) * 4,
                       B + (size_t)(n0 + row) * K + k0 + c4 * 8);
            cp_async16(db + (uint32_t)(row * PADK + c4 * 8 + 4) * 4,
                       B + (size_t)(n0 + row) * K + k0 + c4 * 8 + 4);
        }
        CP_COMMIT();
    };

    stage(0, 0);
    int buf = 0;
    const int q2 = (lane & 3) * 2;
    const int rr = lane >> 2;

    for (int c = 0; c < T; ++c) {
        if (c + 1 < T) { stage(c + 1, buf ^ 1); CP_WAIT(1); }
        else           { CP_WAIT(0); }
        __syncthreads();

        const float* As = sm + buf * STAGE_W64_F;
        const float* Bs = As + A_TILE_F;
#pragma unroll
        for (int ks = 0; ks < 4; ++ks) {
            uint32_t a[4][4];
            const int cc = ks * 8 + q2;
#pragma unroll
            for (int mi = 0; mi < 4; ++mi) {
                const float* p = As + (wm * 64 + mi * 16 + rr) * PADK + cc;
                float2 lo = *(const float2*)p;
                float2 hi = *(const float2*)(p + 8 * PADK);
                a[mi][0] = __float_as_uint(lo.x);
                a[mi][1] = __float_as_uint(hi.x);
                a[mi][2] = __float_as_uint(lo.y);
                a[mi][3] = __float_as_uint(hi.y);
            }
#pragma unroll
            for (int ni = 0; ni < 8; ++ni) {
                const float* p = Bs + (wn * 64 + ni * 8 + rr) * PADK + cc;
                float2 v = *(const float2*)p;
                uint32_t b0 = __float_as_uint(v.x);
                uint32_t b1 = __float_as_uint(v.y);
#pragma unroll
                for (int mi = 0; mi < 4; ++mi)
                    mma_tf32(acc[mi][ni], a[mi][0], a[mi][1], a[mi][2], a[mi][3],
                             b0, b1);
            }
        }
        __syncthreads();
        buf ^= 1;
    }

#pragma unroll
    for (int ni = 0; ni < 8; ++ni) {
        const int n = n0 + wn * 64 + ni * 8 + 2 * (lane & 3);
        const float bx = __ldg(bias + n), by = __ldg(bias + n + 1);
#pragma unroll
        for (int mi = 0; mi < 4; ++mi) {
            const int m = m0 + wm * 64 + mi * 16 + (lane >> 2);
            float v00 = acc[mi][ni][0] + bx, v01 = acc[mi][ni][1] + by;
            float v10 = acc[mi][ni][2] + bx, v11 = acc[mi][ni][3] + by;
            if (INTERMEDIATE) {
                v00 = cvt_tf32(fmaxf(v00, 0.f)); v01 = cvt_tf32(fmaxf(v01, 0.f));
                v10 = cvt_tf32(fmaxf(v10, 0.f)); v11 = cvt_tf32(fmaxf(v11, 0.f));
                const int g = n & ~7;
                const int p0 = g | perm8(n & 7), p1 = g | perm8((n + 1) & 7);
                C[(size_t)m * N + p0] = v00;
                C[(size_t)m * N + p1] = v01;
                C[(size_t)(m + 8) * N + p0] = v10;
                C[(size_t)(m + 8) * N + p1] = v11;
            } else {
                *(float2*)(C + (size_t)m * N + n) = make_float2(v00, v01);
                *(float2*)(C + (size_t)(m + 8) * N + n) = make_float2(v10, v11);
            }
        }
    }
}

// ---------------------------------------------------------------------------
// Proven 256-thr BN=128 GEMM — kept for gemm2.
// ---------------------------------------------------------------------------
template <bool INTERMEDIATE>
__global__ __launch_bounds__(256, 2)
void sage_mma_gemm(const float* __restrict__ A0, const float* __restrict__ A1,
                   const float* __restrict__ B0t, const float* __restrict__ B1t,
                   const float* __restrict__ bias, float* __restrict__ C,
                   int K, int N) {
    extern __shared__ float sm[];
    const uint32_t sbase = smem_u32(sm);
    const int tid = threadIdx.x, lane = tid & 31, w = tid >> 5;
    const int wm = w >> 2, wn = w & 3;
    const int m0 = blockIdx.y * 128, n0 = blockIdx.x * 128;
    const int kc = K / 32;
    const int T = 2 * kc;

    float acc[4][4][4];
#pragma unroll
    for (int mi = 0; mi < 4; ++mi)
#pragma unroll
        for (int ni = 0; ni < 4; ++ni)
#pragma unroll
            for (int r = 0; r < 4; ++r) acc[mi][ni][r] = 0.f;

    const int srow = tid >> 3, sc4 = tid & 7;

    auto stage = [&](int chunk, int buf) {
        const int pair = (chunk >= kc) ? 1 : 0;
        const int k0 = (pair ? chunk - kc : chunk) * 32;
        const float* A = pair ? A1 : A0;
        const float* B = pair ? B1t : B0t;
        const uint32_t da = sbase + (uint32_t)buf * (A_TILE_F * 4);
        const uint32_t db = sbase + (uint32_t)(2 + buf) * (A_TILE_F * 4);
#pragma unroll
        for (int l = 0; l < 4; ++l) {
            int row = srow + l * 32;
            cp_async16(da + (uint32_t)(row * PADK + sc4 * 4) * 4,
                       A + (size_t)(m0 + row) * K + k0 + sc4 * 4);
        }
#pragma unroll
        for (int l = 0; l < 4; ++l) {
            int row = srow + l * 32;
            cp_async16(db + (uint32_t)(row * PADK + sc4 * 4) * 4,
                       B + (size_t)(n0 + row) * K + k0 + sc4 * 4);
        }
        CP_COMMIT();
    };

    stage(0, 0);
    int buf = 0;
    const int q2 = (lane & 3) * 2;
    const int rr = lane >> 2;

    for (int c = 0; c < T; ++c) {
        if (c + 1 < T) { stage(c + 1, buf ^ 1); CP_WAIT(1); }
        else           { CP_WAIT(0); }
        __syncthreads();

        const float* As = sm + buf * A_TILE_F;
        const float* Bs = sm + (2 + buf) * A_TILE_F;
#pragma unroll
        for (int ks = 0; ks < 4; ++ks) {
            uint32_t a[4][4], b[4][2];
            const int cc = ks * 8 + q2;
#pragma unroll
            for (int mi = 0; mi < 4; ++mi) {
                const float* p = As + (wm * 64 + mi * 16 + rr) * PADK + cc;
                float2 lo = *(const float2*)p;
                float2 hi = *(const float2*)(p + 8 * PADK);
                a[mi][0] = __float_as_uint(lo.x);
                a[mi][1] = __float_as_uint(hi.x);
                a[mi][2] = __float_as_uint(lo.y);
                a[mi][3] = __float_as_uint(hi.y);
            }
#pragma unroll
            for (int ni = 0; ni < 4; ++ni) {
                const float* p = Bs + (wn * 32 + ni * 8 + rr) * PADK + cc;
                float2 v = *(const float2*)p;
                b[ni][0] = __float_as_uint(v.x);
                b[ni][1] = __float_as_uint(v.y);
            }
#pragma unroll
            for (int mi = 0; mi < 4; ++mi)
#pragma unroll
                for (int ni = 0; ni < 4; ++ni)
                    mma_tf32(acc[mi][ni], a[mi][0], a[mi][1], a[mi][2], a[mi][3],
                             b[ni][0], b[ni][1]);
        }
        __syncthreads();
        buf ^= 1;
    }

#pragma unroll
    for (int ni = 0; ni < 4; ++ni) {
        const int n = n0 + wn * 32 + ni * 8 + 2 * (lane & 3);
        const float bx = __ldg(bias + n), by = __ldg(bias + n + 1);
#pragma unroll
        for (int mi = 0; mi < 4; ++mi) {
            const int m = m0 + wm * 64 + mi * 16 + (lane >> 2);
            float v00 = acc[mi][ni][0] + bx, v01 = acc[mi][ni][1] + by;
            float v10 = acc[mi][ni][2] + bx, v11 = acc[mi][ni][3] + by;
            if (INTERMEDIATE) {
                v00 = cvt_tf32(fmaxf(v00, 0.f)); v01 = cvt_tf32(fmaxf(v01, 0.f));
                v10 = cvt_tf32(fmaxf(v10, 0.f)); v11 = cvt_tf32(fmaxf(v11, 0.f));
                const int g = n & ~7;
                const int p0 = g | perm8(n & 7), p1 = g | perm8((n + 1) & 7);
                C[(size_t)m * N + p0] = v00;
                C[(size_t)m * N + p1] = v01;
                C[(size_t)(m + 8) * N + p0] = v10;
                C[(size_t)(m + 8) * N + p1] = v11;
            } else {
                *(float2*)(C + (size_t)m * N + n) = make_float2(v00, v01);
                *(float2*)(C + (size_t)(m + 8) * N + n) = make_float2(v10, v11);
            }
        }
    }
}

// ---------------------------------------------------------------------------
extern "C" void kernel_launch(void* const* d_in, const int* in_sizes, int n_in,
                              void* d_out, int out_size) {
    const float* x   = (const float*)d_in[0];
    const float* Ws0 = (const float*)d_in[1];
    const float* Wn0 = (const float*)d_in[2];
    const float* b0  = (const float*)d_in[3];
    const float* Ws1 = (const float*)d_in[4];
    const float* Wn1 = (const float*)d_in[5];
    const float* b1  = (const float*)d_in[6];
    const float* Ws2 = (const float*)d_in[7];
    const float* Wn2 = (const float*)d_in[8];
    const float* b2  = (const float*)d_in[9];
    const int*   e0  = (const int*)d_in[10];
    const int*   e1  = (const int*)d_in[11];
    const int*   e2  = (const int*)d_in[12];
    float* out = (float*)d_out;

    float *xr, *neigh0, *h1, *neigh1, *h2, *neigh2;
    float *Wt0s, *Wt0n, *Wt1s, *Wt1n, *Wt2s, *Wt2n;
    cudaGetSymbolAddress((void**)&xr,     g_xr);
    cudaGetSymbolAddress((void**)&neigh0, g_neigh0);
    cudaGetSymbolAddress((void**)&h1,     g_h1);
    cudaGetSymbolAddress((void**)&neigh1, g_neigh1);
    cudaGetSymbolAddress((void**)&h2,     g_h2);
    cudaGetSymbolAddress((void**)&neigh2, g_neigh2);
    cudaGetSymbolAddress((void**)&Wt0s,   g_Wt0s);
    cudaGetSymbolAddress((void**)&Wt0n,   g_Wt0n);
    cudaGetSymbolAddress((void**)&Wt1s,   g_Wt1s);
    cudaGetSymbolAddress((void**)&Wt1n,   g_Wt1n);
    cudaGetSymbolAddress((void**)&Wt2s,   g_Wt2s);
    cudaGetSymbolAddress((void**)&Wt2n,   g_Wt2n);

    cudaFuncSetAttribute((const void*)layer0_fused_kernel,
                         cudaFuncAttributeMaxDynamicSharedMemorySize, SMEM_GEMM_BYTES);
    cudaFuncSetAttribute((const void*)sage_mma_gemm_w64<true>,
                         cudaFuncAttributeMaxDynamicSharedMemorySize, SMEM_W64_BYTES);
    cudaFuncSetAttribute((const void*)sage_mma_gemm<false>,
                         cudaFuncAttributeMaxDynamicSharedMemorySize, SMEM_GEMM_BYTES);

    // #1: transposes + flag clear
    transpose_all_kernel<<<1024, dim3(32, 8)>>>(Ws0, Wt0s, Wn0, Wt0n,
                                                Ws1, Wt1s, Wn1, Wt1n,
                                                Ws2, Wt2s, Wn2, Wt2n);
    // #2: fused layer 0 (R8-exact)
    layer0_fused_kernel<<<GATHER_CTAS + 4 * NUNITS, 256, SMEM_GEMM_BYTES>>>(
        x, e0, neigh0, xr, Wt0s, Wt0n, b0, h1);
    // #3: gather1 (whole-chip)
    gather_mean_kernel<<<N2_SZ / 4, dim3(H_DIM / 8, 4)>>>(h1, e1, neigh1, H_DIM / 8, N2_SZ);
    // #4: Layer-1 dual GEMM — NEW 64x64-warp-tile kernel (smem-BW test)
    sage_mma_gemm_w64<true><<<dim3(H_DIM / 128, N2_SZ / 128), 128, SMEM_W64_BYTES>>>(
        h1, neigh1, Wt1s, Wt1n, b1, h2, H_DIM, H_DIM);
    // #5: gather2
    gather_mean_kernel<<<SEEDS_SZ / 4, dim3(H_DIM / 8, 4)>>>(h2, e2, neigh2, H_DIM / 8, SEEDS_SZ);
    // #6: Layer-2 dual GEMM (proven kernel)
    sage_mma_gemm<false><<<dim3(C_DIM / 128, SEEDS_SZ / 128), 256, SMEM_GEMM_BYTES>>>(
        h2, neigh2, Wt2s, Wt2n, b2, out, H_DIM, C_DIM);
}

// round 17
// speedup vs baseline: 1.4733x; 1.4733x over previous
#include <cuda_runtime.h>
#include <cuda_fp16.h>
#include <cstdint>
#include <cstddef>

// ---------------- problem constants ----------------
#define FANOUT 10
#define N0_SZ 1362944
#define N1_SZ 123904
#define N2_SZ 11264
#define SEEDS_SZ 1024
#define IN_DIM 256
#define H_DIM 512
#define C_DIM 256

#define NUNITS (N1_SZ / 128)        // 968 layer-0 M-tiles
#define GATHER_CTAS 96

// ---------------- device scratch (allocation-free rule) ----------------
__device__ __align__(16) __half g_xr[(size_t)N1_SZ * IN_DIM];
__device__ __align__(16) __half g_neigh0[(size_t)N1_SZ * IN_DIM];
__device__ __align__(16) __half g_h1[(size_t)N1_SZ * H_DIM];
__device__ __align__(16) __half g_neigh1[(size_t)N2_SZ * H_DIM];
__device__ __align__(16) __half g_h2[(size_t)N2_SZ * H_DIM];
__device__ __align__(16) __half g_neigh2[(size_t)SEEDS_SZ * H_DIM];
__device__ __align__(16) __half g_Wt0s[(size_t)H_DIM * IN_DIM];
__device__ __align__(16) __half g_Wt0n[(size_t)H_DIM * IN_DIM];
__device__ __align__(16) __half g_Wt1s[(size_t)H_DIM * H_DIM];
__device__ __align__(16) __half g_Wt1n[(size_t)H_DIM * H_DIM];
__device__ __align__(16) __half g_Wt2s[(size_t)C_DIM * H_DIM];
__device__ __align__(16) __half g_Wt2n[(size_t)C_DIM * H_DIM];
__device__ volatile unsigned g_ready0[NUNITS];

// ---------------- helpers ----------------
__device__ __forceinline__ uint32_t smem_u32(const void* p) {
    uint32_t a;
    asm("{ .reg .u64 t; cvta.to.shared.u64 t, %1; cvt.u32.u64 %0, t; }" : "=r"(a) : "l"(p));
    return a;
}
__device__ __forceinline__ void cp_async16(uint32_t dst, const void* src) {
    asm volatile("cp.async.cg.shared.global [%0], [%1], 16;" :: "r"(dst), "l"(src));
}
#define CP_COMMIT() asm volatile("cp.async.commit_group;" ::: "memory")
#define CP_WAIT(n)  asm volatile("cp.async.wait_group %0;" :: "n"(n) : "memory")

// fp16 tensor-core MMA, fp32 accumulate (sm_80+ portable)
__device__ __forceinline__ void mma_f16(float c[4],
                                        uint32_t a0, uint32_t a1, uint32_t a2, uint32_t a3,
                                        uint32_t b0, uint32_t b1) {
    asm volatile(
        "mma.sync.aligned.m16n8k16.row.col.f32.f16.f16.f32 "
        "{%0,%1,%2,%3}, {%4,%5,%6,%7}, {%8,%9}, {%0,%1,%2,%3};"
        : "+f"(c[0]), "+f"(c[1]), "+f"(c[2]), "+f"(c[3])
        : "r"(a0), "r"(a1), "r"(a2), "r"(a3), "r"(b0), "r"(b1));
}

#define PADH 40                              // padded halves per smem row
#define A_TILE_H (128 * PADH)                // 5120 halves = 10240 bytes
#define STAGE_H  (2 * A_TILE_H)              // A tile + B tile per stage
#define SMEM_GEMM_BYTES (2 * STAGE_H * 2)    // 2 stages: 40KB

// ---------------------------------------------------------------------------
// Layer-0 fused producer/consumer kernel (R8 structure, fp16 data).
// ---------------------------------------------------------------------------
__global__ __launch_bounds__(256, 2)
void layer0_fused_kernel(const float* __restrict__ x, const int* __restrict__ e0,
                         __half* __restrict__ neigh0, __half* __restrict__ xr,
                         const __half* __restrict__ B0t, const __half* __restrict__ B1t,
                         const float* __restrict__ bias, __half* __restrict__ C) {
    extern __shared__ char smc[];
    const int tid = threadIdx.x;

    if (blockIdx.x < GATHER_CTAS) {
        const int t = tid & 31;          // 32 threads x 8 floats = 256 cols
        const int ry = tid >> 5;
        const int dim8 = IN_DIM / 8;     // 32
        const float4* x4 = (const float4*)x;

        for (int u = blockIdx.x; u < NUNITS; u += GATHER_CTAS) {
            const int dbase = u * 128;
#pragma unroll 1
            for (int pass = 0; pass < 16; ++pass) {
                const int d = dbase + pass * 8 + ry;
                const int* s = e0 + (size_t)d * FANOUT;

                float4 a0 = make_float4(0.f, 0.f, 0.f, 0.f);
                float4 a1 = make_float4(0.f, 0.f, 0.f, 0.f);
#pragma unroll
                for (int e = 0; e < FANOUT; ++e) {
                    int r = __ldg(s + e);
                    const float4* p = x4 + ((size_t)r * dim8 + t) * 2;
                    float4 v0 = __ldg(p), v1 = __ldg(p + 1);
                    a0.x += v0.x; a0.y += v0.y; a0.z += v0.z; a0.w += v0.w;
                    a1.x += v1.x; a1.y += v1.y; a1.z += v1.z; a1.w += v1.w;
                }
                const float inv = 1.0f / FANOUT;
                uint4 o;
                *(__half2*)&o.x = __floats2half2_rn(a0.x * inv, a0.y * inv);
                *(__half2*)&o.y = __floats2half2_rn(a0.z * inv, a0.w * inv);
                *(__half2*)&o.z = __floats2half2_rn(a1.x * inv, a1.y * inv);
                *(__half2*)&o.w = __floats2half2_rn(a1.z * inv, a1.w * inv);
                ((uint4*)(neigh0 + (size_t)d * IN_DIM))[t] = o;

                const float4* p = x4 + ((size_t)d * dim8 + t) * 2;
                float4 v0 = __ldg(p), v1 = __ldg(p + 1);
                uint4 ox;
                *(__half2*)&ox.x = __floats2half2_rn(v0.x, v0.y);
                *(__half2*)&ox.y = __floats2half2_rn(v0.z, v0.w);
                *(__half2*)&ox.z = __floats2half2_rn(v1.x, v1.y);
                *(__half2*)&ox.w = __floats2half2_rn(v1.z, v1.w);
                ((uint4*)(xr + (size_t)d * IN_DIM))[t] = ox;
            }
            __threadfence();
            __syncthreads();
            if (tid == 0) g_ready0[u] = 1;
        }
        return;
    }

    // ---- GEMM consumer (K=256, N=512, BN=128, fp16 operands) ----
    const int gbid = (int)blockIdx.x - GATHER_CTAS;
    const int n0 = (gbid & 3) * 128;
    const int mu = gbid >> 2;
    const int m0 = mu * 128;

    if (tid == 0) {
        while (g_ready0[mu] == 0) { __nanosleep(128); }
    }
    __syncthreads();

    __half* smh = (__half*)smc;
    const uint32_t sbase = smem_u32(smc);
    const int lane = tid & 31, w = tid >> 5;
    const int wm = w >> 2, wn = w & 3;
    const int K = IN_DIM, N = H_DIM;
    const int kc = K / 32, T = 2 * kc;

    float acc[4][4][4];
#pragma unroll
    for (int mi = 0; mi < 4; ++mi)
#pragma unroll
        for (int ni = 0; ni < 4; ++ni)
#pragma unroll
            for (int r = 0; r < 4; ++r) acc[mi][ni][r] = 0.f;

    auto stage = [&](int chunk, int buf) {
        const int pair = (chunk >= kc) ? 1 : 0;
        const int k0 = (pair ? chunk - kc : chunk) * 32;
        const __half* A = pair ? neigh0 : xr;
        const __half* B = pair ? B1t : B0t;
        const uint32_t da = sbase + (uint32_t)(buf * STAGE_H) * 2;
        const uint32_t db = da + (uint32_t)A_TILE_H * 2;
        // A: 128 rows x 32 halves = 64B/row = 512 cp16 -> 2/thread
#pragma unroll
        for (int l = 0; l < 2; ++l) {
            int i = tid + l * 256;
            int row = i >> 2, c4 = i & 3;
            cp_async16(da + (uint32_t)(row * PADH + c4 * 8) * 2,
                       A + (size_t)(m0 + row) * K + k0 + c4 * 8);
        }
#pragma unroll
        for (int l = 0; l < 2; ++l) {
            int i = tid + l * 256;
            int row = i >> 2, c4 = i & 3;
            cp_async16(db + (uint32_t)(row * PADH + c4 * 8) * 2,
                       B + (size_t)(n0 + row) * K + k0 + c4 * 8);
        }
        CP_COMMIT();
    };

    stage(0, 0);
    int buf = 0;
    const int q2 = (lane & 3) * 2;
    const int rr = lane >> 2;

    for (int c = 0; c < T; ++c) {
        if (c + 1 < T) { stage(c + 1, buf ^ 1); CP_WAIT(1); }
        else           { CP_WAIT(0); }
        __syncthreads();

        const __half* As = smh + buf * STAGE_H;
        const __half* Bs = As + A_TILE_H;
#pragma unroll
        for (int ks = 0; ks < 2; ++ks) {      // 2 x K=16 steps per 32-chunk
            const int kb = ks * 16 + q2;
            uint32_t a[4][4], b[4][2];
#pragma unroll
            for (int mi = 0; mi < 4; ++mi) {
                const __half* p = As + (wm * 64 + mi * 16 + rr) * PADH + kb;
                a[mi][0] = *(const uint32_t*)p;
                a[mi][1] = *(const uint32_t*)(p + 8 * PADH);
                a[mi][2] = *(const uint32_t*)(p + 8);
                a[mi][3] = *(const uint32_t*)(p + 8 * PADH + 8);
            }
#pragma unroll
            for (int ni = 0; ni < 4; ++ni) {
                const __half* p = Bs + (wn * 32 + ni * 8 + rr) * PADH + kb;
                b[ni][0] = *(const uint32_t*)p;
                b[ni][1] = *(const uint32_t*)(p + 8);
            }
#pragma unroll
            for (int mi = 0; mi < 4; ++mi)
#pragma unroll
                for (int ni = 0; ni < 4; ++ni)
                    mma_f16(acc[mi][ni], a[mi][0], a[mi][1], a[mi][2], a[mi][3],
                            b[ni][0], b[ni][1]);
        }
        __syncthreads();
        buf ^= 1;
    }

    // epilogue: bias + ReLU, store half2 (feeds layer 1)
#pragma unroll
    for (int ni = 0; ni < 4; ++ni) {
        const int n = n0 + wn * 32 + ni * 8 + 2 * (lane & 3);
        const float bx = __ldg(bias + n), by = __ldg(bias + n + 1);
#pragma unroll
        for (int mi = 0; mi < 4; ++mi) {
            const int m = m0 + wm * 64 + mi * 16 + (lane >> 2);
            float v00 = fmaxf(acc[mi][ni][0] + bx, 0.f);
            float v01 = fmaxf(acc[mi][ni][1] + by, 0.f);
            float v10 = fmaxf(acc[mi][ni][2] + bx, 0.f);
            float v11 = fmaxf(acc[mi][ni][3] + by, 0.f);
            *(__half2*)(C + (size_t)m * N + n)       = __floats2half2_rn(v00, v01);
            *(__half2*)(C + (size_t)(m + 8) * N + n) = __floats2half2_rn(v10, v11);
        }
    }
}

// ---------------------------------------------------------------------------
// gather-mean on half data (gather1, gather2) — whole-chip.
// blockDim = (dim/8, rowsPerBlk); each thread handles 8 halves.
// ---------------------------------------------------------------------------
__global__ void gather_mean_half(const __half* __restrict__ h,
                                 const int* __restrict__ src,
                                 __half* __restrict__ out, int dim8, int num_dst) {
    const int d = blockIdx.x * blockDim.y + threadIdx.y;
    if (d >= num_dst) return;
    const int t = threadIdx.x;
    const int* s = src + (size_t)d * FANOUT;
    const uint4* h4 = (const uint4*)h;       // row stride = dim8 uint4s

    float acc[8];
#pragma unroll
    for (int j = 0; j < 8; ++j) acc[j] = 0.f;
#pragma unroll
    for (int e = 0; e < FANOUT; ++e) {
        int r = __ldg(s + e);
        uint4 v = __ldg(h4 + (size_t)r * dim8 + t);
        const __half2* hp = (const __half2*)&v;
#pragma unroll
        for (int j = 0; j < 4; ++j) {
            float2 f = __half22float2(hp[j]);
            acc[2 * j]     += f.x;
            acc[2 * j + 1] += f.y;
        }
    }
    const float inv = 1.0f / FANOUT;
    uint4 o;
    *(__half2*)&o.x = __floats2half2_rn(acc[0] * inv, acc[1] * inv);
    *(__half2*)&o.y = __floats2half2_rn(acc[2] * inv, acc[3] * inv);
    *(__half2*)&o.z = __floats2half2_rn(acc[4] * inv, acc[5] * inv);
    *(__half2*)&o.w = __floats2half2_rn(acc[6] * inv, acc[7] * inv);
    ((uint4*)out)[(size_t)d * dim8 + t] = o;
}

// ---------------------------------------------------------------------------
// Merged weight transpose -> half (6 jobs) + flag clear, ONE launch.
// Wt[n][k] = (half)W[k][n], no permutation (fp16 fragments use natural order).
// ---------------------------------------------------------------------------
__global__ void transpose_all_kernel(const float* W0, __half* D0,
                                     const float* W1, __half* D1,
                                     const float* W2, __half* D2,
                                     const float* W3, __half* D3,
                                     const float* W4, __half* D4,
                                     const float* W5, __half* D5) {
    const int b = blockIdx.x;
    const int tid = threadIdx.y * 32 + threadIdx.x;
    if (b == 0) {
        for (int i = tid; i < NUNITS; i += 256) g_ready0[i] = 0;
    }
    const float* W; __half* Wt; int K, N, t;
    if (b < 256) {
        K = IN_DIM; N = H_DIM;
        if (b < 128) { W = W0; Wt = D0; t = b; }
        else         { W = W1; Wt = D1; t = b - 128; }
    } else if (b < 768) {
        K = H_DIM; N = H_DIM;
        if (b < 512) { W = W2; Wt = D2; t = b - 256; }
        else         { W = W3; Wt = D3; t = b - 512; }
    } else {
        K = H_DIM; N = C_DIM;
        if (b < 896) { W = W4; Wt = D4; t = b - 768; }
        else         { W = W5; Wt = D5; t = b - 896; }
    }
    const int ntx = N / 32;
    const int bx = (t % ntx) * 32, by = (t / ntx) * 32;

    __shared__ float tile[32][33];
#pragma unroll
    for (int i = threadIdx.y; i < 32; i += 8)
        tile[i][threadIdx.x] = __ldg(W + (size_t)(by + i) * N + bx + threadIdx.x);
    __syncthreads();
#pragma unroll
    for (int i = threadIdx.y; i < 32; i += 8)
        Wt[(size_t)(bx + i) * K + by + threadIdx.x] = __float2half(tile[threadIdx.x][i]);
}

// ---------------------------------------------------------------------------
// fp16 dual-GEMM (standalone, gemm1 + gemm2). BN=128, BK=32, 8 warps 2m x 4n.
// OUT_HALF: half output (intermediate) vs fp32 (final).
// ---------------------------------------------------------------------------
template <bool RELU, bool OUT_HALF>
__global__ __launch_bounds__(256, 2)
void sage_mma_gemm_f16(const __half* __restrict__ A0, const __half* __restrict__ A1,
                       const __half* __restrict__ B0t, const __half* __restrict__ B1t,
                       const float* __restrict__ bias, void* __restrict__ Cv,
                       int K, int N) {
    extern __shared__ char smc[];
    __half* smh = (__half*)smc;
    const uint32_t sbase = smem_u32(smc);
    const int tid = threadIdx.x, lane = tid & 31, w = tid >> 5;
    const int wm = w >> 2, wn = w & 3;
    const int m0 = blockIdx.y * 128, n0 = blockIdx.x * 128;
    const int kc = K / 32, T = 2 * kc;

    float acc[4][4][4];
#pragma unroll
    for (int mi = 0; mi < 4; ++mi)
#pragma unroll
        for (int ni = 0; ni < 4; ++ni)
#pragma unroll
            for (int r = 0; r < 4; ++r) acc[mi][ni][r] = 0.f;

    auto stage = [&](int chunk, int buf) {
        const int pair = (chunk >= kc) ? 1 : 0;
        const int k0 = (pair ? chunk - kc : chunk) * 32;
        const __half* A = pair ? A1 : A0;
        const __half* B = pair ? B1t : B0t;
        const uint32_t da = sbase + (uint32_t)(buf * STAGE_H) * 2;
        const uint32_t db = da + (uint32_t)A_TILE_H * 2;
#pragma unroll
        for (int l = 0; l < 2; ++l) {
            int i = tid + l * 256;
            int row = i >> 2, c4 = i & 3;
            cp_async16(da + (uint32_t)(row * PADH + c4 * 8) * 2,
                       A + (size_t)(m0 + row) * K + k0 + c4 * 8);
        }
#pragma unroll
        for (int l = 0; l < 2; ++l) {
            int i = tid + l * 256;
            int row = i >> 2, c4 = i & 3;
            cp_async16(db + (uint32_t)(row * PADH + c4 * 8) * 2,
                       B + (size_t)(n0 + row) * K + k0 + c4 * 8);
        }
        CP_COMMIT();
    };

    stage(0, 0);
    int buf = 0;
    const int q2 = (lane & 3) * 2;
    const int rr = lane >> 2;

    for (int c = 0; c < T; ++c) {
        if (c + 1 < T) { stage(c + 1, buf ^ 1); CP_WAIT(1); }
        else           { CP_WAIT(0); }
        __syncthreads();

        const __half* As = smh + buf * STAGE_H;
        const __half* Bs = As + A_TILE_H;
#pragma unroll
        for (int ks = 0; ks < 2; ++ks) {
            const int kb = ks * 16 + q2;
            uint32_t a[4][4], b[4][2];
#pragma unroll
            for (int mi = 0; mi < 4; ++mi) {
                const __half* p = As + (wm * 64 + mi * 16 + rr) * PADH + kb;
                a[mi][0] = *(const uint32_t*)p;
                a[mi][1] = *(const uint32_t*)(p + 8 * PADH);
                a[mi][2] = *(const uint32_t*)(p + 8);
                a[mi][3] = *(const uint32_t*)(p + 8 * PADH + 8);
            }
#pragma unroll
            for (int ni = 0; ni < 4; ++ni) {
                const __half* p = Bs + (wn * 32 + ni * 8 + rr) * PADH + kb;
                b[ni][0] = *(const uint32_t*)p;
                b[ni][1] = *(const uint32_t*)(p + 8);
            }
#pragma unroll
            for (int mi = 0; mi < 4; ++mi)
#pragma unroll
                for (int ni = 0; ni < 4; ++ni)
                    mma_f16(acc[mi][ni], a[mi][0], a[mi][1], a[mi][2], a[mi][3],
                            b[ni][0], b[ni][1]);
        }
        __syncthreads();
        buf ^= 1;
    }

#pragma unroll
    for (int ni = 0; ni < 4; ++ni) {
        const int n = n0 + wn * 32 + ni * 8 + 2 * (lane & 3);
        const float bx = __ldg(bias + n), by = __ldg(bias + n + 1);
#pragma unroll
        for (int mi = 0; mi < 4; ++mi) {
            const int m = m0 + wm * 64 + mi * 16 + (lane >> 2);
            float v00 = acc[mi][ni][0] + bx, v01 = acc[mi][ni][1] + by;
            float v10 = acc[mi][ni][2] + bx, v11 = acc[mi][ni][3] + by;
            if (RELU) {
                v00 = fmaxf(v00, 0.f); v01 = fmaxf(v01, 0.f);
                v10 = fmaxf(v10, 0.f); v11 = fmaxf(v11, 0.f);
            }
            if (OUT_HALF) {
                __half* C = (__half*)Cv;
                *(__half2*)(C + (size_t)m * N + n)       = __floats2half2_rn(v00, v01);
                *(__half2*)(C + (size_t)(m + 8) * N + n) = __floats2half2_rn(v10, v11);
            } else {
                float* C = (float*)Cv;
                *(float2*)(C + (size_t)m * N + n)       = make_float2(v00, v01);
                *(float2*)(C + (size_t)(m + 8) * N + n) = make_float2(v10, v11);
            }
        }
    }
}

// ---------------------------------------------------------------------------
extern "C" void kernel_launch(void* const* d_in, const int* in_sizes, int n_in,
                              void* d_out, int out_size) {
    const float* x   = (const float*)d_in[0];
    const float* Ws0 = (const float*)d_in[1];
    const float* Wn0 = (const float*)d_in[2];
    const float* b0  = (const float*)d_in[3];
    const float* Ws1 = (const float*)d_in[4];
    const float* Wn1 = (const float*)d_in[5];
    const float* b1  = (const float*)d_in[6];
    const float* Ws2 = (const float*)d_in[7];
    const float* Wn2 = (const float*)d_in[8];
    const float* b2  = (const float*)d_in[9];
    const int*   e0  = (const int*)d_in[10];
    const int*   e1  = (const int*)d_in[11];
    const int*   e2  = (const int*)d_in[12];
    float* out = (float*)d_out;

    __half *xr, *neigh0, *h1, *neigh1, *h2, *neigh2;
    __half *Wt0s, *Wt0n, *Wt1s, *Wt1n, *Wt2s, *Wt2n;
    cudaGetSymbolAddress((void**)&xr,     g_xr);
    cudaGetSymbolAddress((void**)&neigh0, g_neigh0);
    cudaGetSymbolAddress((void**)&h1,     g_h1);
    cudaGetSymbolAddress((void**)&neigh1, g_neigh1);
    cudaGetSymbolAddress((void**)&h2,     g_h2);
    cudaGetSymbolAddress((void**)&neigh2, g_neigh2);
    cudaGetSymbolAddress((void**)&Wt0s,   g_Wt0s);
    cudaGetSymbolAddress((void**)&Wt0n,   g_Wt0n);
    cudaGetSymbolAddress((void**)&Wt1s,   g_Wt1s);
    cudaGetSymbolAddress((void**)&Wt1n,   g_Wt1n);
    cudaGetSymbolAddress((void**)&Wt2s,   g_Wt2s);
    cudaGetSymbolAddress((void**)&Wt2n,   g_Wt2n);

    cudaFuncSetAttribute((const void*)layer0_fused_kernel,
                         cudaFuncAttributeMaxDynamicSharedMemorySize, SMEM_GEMM_BYTES);
    cudaFuncSetAttribute((const void*)sage_mma_gemm_f16<true, true>,
                         cudaFuncAttributeMaxDynamicSharedMemorySize, SMEM_GEMM_BYTES);
    cudaFuncSetAttribute((const void*)sage_mma_gemm_f16<false, false>,
                         cudaFuncAttributeMaxDynamicSharedMemorySize, SMEM_GEMM_BYTES);

    // #1: transposes (fp32 -> half) + flag clear
    transpose_all_kernel<<<1024, dim3(32, 8)>>>(Ws0, Wt0s, Wn0, Wt0n,
                                                Ws1, Wt1s, Wn1, Wt1n,
                                                Ws2, Wt2s, Wn2, Wt2n);
    // #2: fused layer 0 (96 gather producers + 3872 fp16 GEMM consumers)
    layer0_fused_kernel<<<GATHER_CTAS + 4 * NUNITS, 256, SMEM_GEMM_BYTES>>>(
        x, e0, neigh0, xr, Wt0s, Wt0n, b0, h1);
    // #3: gather1 (whole-chip, half data)
    gather_mean_half<<<N2_SZ / 4, dim3(H_DIM / 8, 4)>>>(h1, e1, neigh1, H_DIM / 8, N2_SZ);
    // #4: Layer-1 dual GEMM (fp16, half output)
    sage_mma_gemm_f16<true, true><<<dim3(H_DIM / 128, N2_SZ / 128), 256, SMEM_GEMM_BYTES>>>(
        h1, neigh1, Wt1s, Wt1n, b1, h2, H_DIM, H_DIM);
    // #5: gather2
    gather_mean_half<<<SEEDS_SZ / 4, dim3(H_DIM / 8, 4)>>>(h2, e2, neigh2, H_DIM / 8, SEEDS_SZ);
    // #6: Layer-2 dual GEMM (fp16 operands, fp32 canonical output)
    sage_mma_gemm_f16<false, false><<<dim3(C_DIM / 128, SEEDS_SZ / 128), 256, SMEM_GEMM_BYTES>>>(
        h2, neigh2, Wt2s, Wt2n, b2, out, H_DIM, C_DIM);
}